// round 7
// baseline (speedup 1.0000x reference)
#include <cuda_runtime.h>
#include <cuda_bf16.h>
#include <cstdint>

// Problem constants
#define B_    8
#define LQ_   2048
#define LKV_  2048
#define DQ_   512
#define DC_   768
#define ATT_SCALE 0.044194173824159216f   // 1/sqrt(512)

typedef unsigned long long ull;

// ---------------------------------------------------------------------------
// Scratch (device globals — runtime allocation is forbidden)
// ---------------------------------------------------------------------------
__device__ float g_Kp [(size_t)B_ * LKV_ * DQ_];   // key   @ Wk + bk        (134 MB)
__device__ float g_Vp [(size_t)B_ * LKV_ * DQ_];   // value @ (Wv@Wo)        (134 MB)
__device__ float g_E  [(size_t)B_ * LQ_  * LKV_];  // exp(scale * Q Kp^T)    (134 MB)
__device__ float g_R  [(size_t)B_ * LQ_];          // reciprocal row sums
__device__ float g_Wvo[(size_t)DC_ * DQ_];         // Wv @ Wo
__device__ float g_bo2[DQ_];                       // bv @ Wo + bo

// ---------------------------------------------------------------------------
// f32x2 packed-FMA helpers (sm_100+; FFMA2 only reachable via PTX)
// ---------------------------------------------------------------------------
__device__ __forceinline__ void fma2(ull& d, ull a, ull b) {
    asm("fma.rn.f32x2 %0, %1, %2, %0;" : "+l"(d) : "l"(a), "l"(b));
}
__device__ __forceinline__ ull dup2(float x) {
    unsigned u = __float_as_uint(x);
    ull r;
    asm("mov.b64 %0, {%1, %2};" : "=l"(r) : "r"(u), "r"(u));
    return r;
}
__device__ __forceinline__ float2 unpk(ull v) {
    unsigned lo, hi;
    asm("mov.b64 {%0, %1}, %2;" : "=r"(lo), "=r"(hi) : "l"(v));
    return make_float2(__uint_as_float(lo), __uint_as_float(hi));
}

// ---------------------------------------------------------------------------
// Generic tiled SGEMM: C[m,n] = epi( sum_k A[m,k] * B'[k,n] )
//   BT=false: B is [K,N] row-major (NN)
//   BT=true : B is [N,K] row-major (NT, i.e. C = A B^T)
//   epilogue: v = acc*alpha; if DO_EXP v = expf(v); v = v*rowscale[m] + bias[n]
// Tiles: 128x128x16, 256 threads, 8x8 per thread, f32x2 accumulation.
// All problem dims here are multiples of the tile sizes -> no bounds checks.
// ---------------------------------------------------------------------------
template <bool BT, bool DO_EXP>
__global__ __launch_bounds__(256, 2)
void gemm128(const float* __restrict__ A, const float* __restrict__ B,
             float* __restrict__ C, int M, int N, int K,
             long bsA, long bsB, long bsC,
             const float* __restrict__ bias,       // len N or null
             const float* __restrict__ rowscale,   // len B*M or null
             float alpha)
{
    __shared__ float As[16][132];   // stored transposed: As[k][m]
    __shared__ float Bs[16][132];   // Bs[k][n]

    const int tid  = threadIdx.x;
    const int tx   = tid & 15;      // -> 8 output columns
    const int ty   = tid >> 4;      // -> 8 output rows
    const int z    = blockIdx.z;
    const int rowC = blockIdx.y * 128;
    const int colC = blockIdx.x * 128;

    A += (long)z * bsA + (long)rowC * K;
    if (BT) B += (long)z * bsB + (long)colC * K;
    else    B += (long)z * bsB + colC;
    C += (long)z * bsC;

    float4 pA[2], pB[2];

    auto ldA = [&](int kk) {
#pragma unroll
        for (int i = 0; i < 2; i++) {
            int f = tid + i * 256;
            int r = f >> 2, c4 = (f & 3) * 4;
            pA[i] = *(const float4*)(A + (long)r * K + kk + c4);
        }
    };
    auto ldB = [&](int kk) {
#pragma unroll
        for (int i = 0; i < 2; i++) {
            int f = tid + i * 256;
            if (BT) {
                int r = f >> 2, c4 = (f & 3) * 4;
                pB[i] = *(const float4*)(B + (long)r * K + kk + c4);
            } else {
                int r = f >> 5, c4 = (f & 31) * 4;
                pB[i] = *(const float4*)(B + (long)(kk + r) * N + c4);
            }
        }
    };
    auto stS = [&]() {
#pragma unroll
        for (int i = 0; i < 2; i++) {
            int f = tid + i * 256;
            {
                int r = f >> 2, c4 = (f & 3) * 4;
                As[c4 + 0][r] = pA[i].x; As[c4 + 1][r] = pA[i].y;
                As[c4 + 2][r] = pA[i].z; As[c4 + 3][r] = pA[i].w;
            }
            if (BT) {
                int r = f >> 2, c4 = (f & 3) * 4;
                Bs[c4 + 0][r] = pB[i].x; Bs[c4 + 1][r] = pB[i].y;
                Bs[c4 + 2][r] = pB[i].z; Bs[c4 + 3][r] = pB[i].w;
            } else {
                int r = f >> 5, c4 = (f & 31) * 4;
                *(float4*)&Bs[r][c4] = pB[i];
            }
        }
    };

    ull acc[8][4];
#pragma unroll
    for (int i = 0; i < 8; i++)
#pragma unroll
        for (int j = 0; j < 4; j++) acc[i][j] = 0ull;

    // prologue: tile 0
    ldA(0); ldB(0); stS();
    __syncthreads();

    for (int kk = 16; kk <= K; kk += 16) {
        if (kk < K) { ldA(kk); ldB(kk); }   // overlap LDG with compute
#pragma unroll
        for (int k = 0; k < 16; k++) {
            const float4     a0 = *(const float4*)    &As[k][ty * 8];
            const float4     a1 = *(const float4*)    &As[k][ty * 8 + 4];
            const ulonglong2 b0 = *(const ulonglong2*)&Bs[k][tx * 8];
            const ulonglong2 b1 = *(const ulonglong2*)&Bs[k][tx * 8 + 4];
            const float av[8] = {a0.x, a0.y, a0.z, a0.w, a1.x, a1.y, a1.z, a1.w};
#pragma unroll
            for (int i = 0; i < 8; i++) {
                ull ad = dup2(av[i]);
                fma2(acc[i][0], ad, b0.x);
                fma2(acc[i][1], ad, b0.y);
                fma2(acc[i][2], ad, b1.x);
                fma2(acc[i][3], ad, b1.y);
            }
        }
        __syncthreads();
        if (kk < K) { stS(); __syncthreads(); }
    }

    // epilogue
    float bq[8];
    if (bias) {
        float4 t0 = *(const float4*)(bias + colC + tx * 8);
        float4 t1 = *(const float4*)(bias + colC + tx * 8 + 4);
        bq[0] = t0.x; bq[1] = t0.y; bq[2] = t0.z; bq[3] = t0.w;
        bq[4] = t1.x; bq[5] = t1.y; bq[6] = t1.z; bq[7] = t1.w;
    } else {
#pragma unroll
        for (int j = 0; j < 8; j++) bq[j] = 0.0f;
    }
    const float* rs = rowscale ? rowscale + (long)z * M : nullptr;

#pragma unroll
    for (int i = 0; i < 8; i++) {
        const int m  = rowC + ty * 8 + i;
        const float rsv = rs ? rs[m] : 1.0f;
        float out[8];
#pragma unroll
        for (int j = 0; j < 4; j++) {
            float2 f = unpk(acc[i][j]);
            out[2 * j] = f.x; out[2 * j + 1] = f.y;
        }
#pragma unroll
        for (int j = 0; j < 8; j++) {
            float v = out[j] * alpha;
            if (DO_EXP) v = __expf(v);
            out[j] = v * rsv + bq[j];
        }
        float* cp = C + (long)m * N + colC + tx * 8;
        *(float4*)cp       = make_float4(out[0], out[1], out[2], out[3]);
        *(float4*)(cp + 4) = make_float4(out[4], out[5], out[6], out[7]);
    }
}

// ---------------------------------------------------------------------------
// Reciprocal row sums of E: R[row] = 1 / sum_k E[row,k].  8 rows per CTA.
// ---------------------------------------------------------------------------
__global__ void rowsum_recip(const float* __restrict__ E, float* __restrict__ R,
                             int ncols)
{
    const int row = blockIdx.x * 8 + threadIdx.y;
    const float4* p = (const float4*)(E + (long)row * ncols);
    float s = 0.0f;
    for (int i = threadIdx.x; i < (ncols >> 2); i += 32) {
        float4 v = p[i];
        s += (v.x + v.y) + (v.z + v.w);
    }
#pragma unroll
    for (int o = 16; o > 0; o >>= 1) s += __shfl_xor_sync(0xffffffffu, s, o);
    if (threadIdx.x == 0) R[row] = 1.0f / s;
}

// ---------------------------------------------------------------------------
// bo2[d] = sum_m bv[m] * Wo[m,d] + bo[d]
// ---------------------------------------------------------------------------
__global__ void make_bo2(const float* __restrict__ bv, const float* __restrict__ Wo,
                         const float* __restrict__ bo, float* __restrict__ bo2)
{
    const int d = blockIdx.x * blockDim.x + threadIdx.x;   // 0..511
    float s = bo[d];
    for (int m = 0; m < DQ_; m++) s += bv[m] * Wo[m * DQ_ + d];
    bo2[d] = s;
}

// ---------------------------------------------------------------------------
// kernel_launch
// ---------------------------------------------------------------------------
extern "C" void kernel_launch(void* const* d_in, const int* in_sizes, int n_in,
                              void* d_out, int out_size)
{
    (void)in_sizes; (void)n_in; (void)out_size;
    const float* query = (const float*)d_in[0];
    const float* key   = (const float*)d_in[1];
    const float* value = (const float*)d_in[2];
    const float* Wk    = (const float*)d_in[3];
    const float* bk    = (const float*)d_in[4];
    const float* Wv    = (const float*)d_in[5];
    const float* bv    = (const float*)d_in[6];
    const float* Wo    = (const float*)d_in[7];
    const float* bo    = (const float*)d_in[8];
    float* out = (float*)d_out;

    float *Kp, *Vp, *E, *R, *Wvo, *bo2;
    cudaGetSymbolAddress((void**)&Kp,  g_Kp);
    cudaGetSymbolAddress((void**)&Vp,  g_Vp);
    cudaGetSymbolAddress((void**)&E,   g_E);
    cudaGetSymbolAddress((void**)&R,   g_R);
    cudaGetSymbolAddress((void**)&Wvo, g_Wvo);
    cudaGetSymbolAddress((void**)&bo2, g_bo2);

    // 0) bo2 = bv @ Wo + bo
    make_bo2<<<2, 256>>>(bv, Wo, bo, bo2);

    // 1) Wvo = Wv @ Wo                      [768,512] = [768,512]@[512,512]
    gemm128<false, false><<<dim3(4, 6, 1), 256>>>(
        Wv, Wo, Wvo, DC_, DQ_, DQ_, 0, 0, 0, nullptr, nullptr, 1.0f);

    // 2) Kp = key @ Wk + bk                 [8,2048,512]
    gemm128<false, false><<<dim3(4, 16, 8), 256>>>(
        key, Wk, Kp, LKV_, DQ_, DC_,
        (long)LKV_ * DC_, 0, (long)LKV_ * DQ_, bk, nullptr, 1.0f);

    // 3) Vp = value @ Wvo                   [8,2048,512]
    gemm128<false, false><<<dim3(4, 16, 8), 256>>>(
        value, Wvo, Vp, LKV_, DQ_, DC_,
        (long)LKV_ * DC_, 0, (long)LKV_ * DQ_, nullptr, nullptr, 1.0f);

    // 4) E = exp(scale * Q @ Kp^T)          [8,2048,2048]
    gemm128<true, true><<<dim3(16, 16, 8), 256>>>(
        query, Kp, E, LQ_, LKV_, DQ_,
        (long)LQ_ * DQ_, (long)LKV_ * DQ_, (long)LQ_ * LKV_,
        nullptr, nullptr, ATT_SCALE);

    // 5) R = 1 / rowsum(E)
    rowsum_recip<<<(B_ * LQ_) / 8, dim3(32, 8)>>>(E, R, LKV_);

    // 6) out = diag(R) * E @ Vp + bo2       [8,2048,512]
    gemm128<false, false><<<dim3(4, 16, 8), 256>>>(
        E, Vp, out, LQ_, DQ_, LKV_,
        (long)LQ_ * LKV_, (long)LKV_ * DQ_, (long)LQ_ * DQ_,
        bo2, R, 1.0f);
}

// round 11
// speedup vs baseline: 2.0097x; 2.0097x over previous
#include <cuda_runtime.h>
#include <cuda_bf16.h>
#include <cstdint>

// ---------------------------------------------------------------------------
// Problem constants
// ---------------------------------------------------------------------------
#define B_    8
#define LQ_   2048
#define LKV_  2048
#define DQ_   512
#define DC_   768
#define ATT_SCALE 0.044194173824159216f   // 1/sqrt(512)

// ---------------------------------------------------------------------------
// Scratch (device globals — runtime allocation is forbidden)
// ---------------------------------------------------------------------------
__device__ float g_Kp  [(size_t)B_ * LKV_ * DQ_];   // key @ Wk + bk          [B,2048,512]
__device__ float g_VpT [(size_t)B_ * DQ_ * LKV_];   // (value @ Wvo)^T        [B,512,2048]
__device__ float g_E   [(size_t)B_ * LQ_ * LKV_];   // exp(scale * Q Kp^T)    [B,2048,2048]
__device__ float g_R   [(size_t)B_ * LQ_];          // reciprocal row sums
__device__ float g_WkT [(size_t)DQ_ * DC_];         // Wk^T   [512,768]
__device__ float g_WoT [(size_t)DQ_ * DQ_];         // Wo^T   [512,512]
__device__ float g_WvoT[(size_t)DQ_ * DC_];         // (Wv@Wo)^T [512,768]
__device__ float g_bo2 [DQ_];                       // bv @ Wo + bo

// ---------------------------------------------------------------------------
// PTX helpers — baseline sm_103 ISA only (NO tcgen05: harness targets sm_103)
// ---------------------------------------------------------------------------
__device__ __forceinline__ uint32_t smem_u32(const void* p) {
    uint32_t a;
    asm("{ .reg .u64 t; cvta.to.shared.u64 t, %1; cvt.u32.u64 %0, t; }"
        : "=r"(a) : "l"(p));
    return a;
}

// ldmatrix x4: four 8x8 b16 tiles (sm_75+, compiles for sm_103 base)
__device__ __forceinline__ void ldsm4(uint32_t* r, uint32_t addr) {
    asm volatile("ldmatrix.sync.aligned.m8n8.x4.shared.b16 {%0,%1,%2,%3}, [%4];"
        : "=r"(r[0]), "=r"(r[1]), "=r"(r[2]), "=r"(r[3]) : "r"(addr));
}

// mma m16n8k16 bf16 -> f32 accumulate (sm_80+, compiles for sm_103 base)
__device__ __forceinline__ void hmma(float* d, const uint32_t* a, const uint32_t* b) {
    asm volatile(
        "mma.sync.aligned.m16n8k16.row.col.f32.bf16.bf16.f32 "
        "{%0,%1,%2,%3}, {%4,%5,%6,%7}, {%8,%9}, {%0,%1,%2,%3};"
        : "+f"(d[0]), "+f"(d[1]), "+f"(d[2]), "+f"(d[3])
        : "r"(a[0]), "r"(a[1]), "r"(a[2]), "r"(a[3]), "r"(b[0]), "r"(b[1]));
}

// Pack two fp32 into bf16x2 (round-to-nearest). First asm source = HIGH half.
__device__ __forceinline__ uint32_t pk2(float lo, float hi) {
    uint32_t r;
    asm("cvt.rn.bf16x2.f32 %0, %1, %2;" : "=r"(r) : "f"(hi), "f"(lo));
    return r;
}
// Split float4 into bf16-hi quad + bf16-lo (residual) quad
__device__ __forceinline__ void split4(float4 v, uint2& h, uint2& l) {
    uint32_t h01 = pk2(v.x, v.y);
    uint32_t h23 = pk2(v.z, v.w);
    float f0 = __uint_as_float(h01 << 16);
    float f1 = __uint_as_float(h01 & 0xffff0000u);
    float f2 = __uint_as_float(h23 << 16);
    float f3 = __uint_as_float(h23 & 0xffff0000u);
    h = make_uint2(h01, h23);
    l = make_uint2(pk2(v.x - f0, v.y - f1), pk2(v.z - f2, v.w - f3));
}

// ---------------------------------------------------------------------------
// Tensor-core NT GEMM, bf16 hi/lo split (fp32-accurate):
//   C[m,n] = epi( sum_k A[m,k] * B[n,k] )   A:[M,K] B:[N,K] row-major fp32
// CTA tile 128x128, K-chunk 32. 8 warps, warp tile 64x32, HMMA m16n8k16.
// Smem bf16 tiles, 80B row pitch (conflict-free ldmatrix: 5r mod 8 bijective).
// Next-chunk LDGs issue before the consumer sync -> latency hidden.
// epilogue: v=acc; if EXP v=expf(v*alpha); if RS v*=R[m]; if BIAS v+=bias[n]
// ---------------------------------------------------------------------------
#define PITCH 80
#define T_AH  0
#define T_AL  10240
#define T_BH  20480
#define T_BL  30720

template <int DO_EXP, int DO_RS, int DO_BIAS>
__global__ __launch_bounds__(256, 2)
void tgemm(const float* __restrict__ A, const float* __restrict__ B,
           float* __restrict__ C, int M, int N, int K,
           long bsA, long bsB, long bsC,
           const float* __restrict__ bias, const float* __restrict__ rowscale,
           float alpha)
{
    __shared__ __align__(128) char sm[40960];
    const uint32_t sbase = smem_u32(sm);

    const int tid  = threadIdx.x;
    const int warp = tid >> 5, ln = tid & 31;
    const int z    = blockIdx.z;
    const int n0   = blockIdx.x * 128;
    const int m0   = blockIdx.y * 128;

    A += (long)z * bsA + (long)m0 * K;
    B += (long)z * bsB + (long)n0 * K;
    C += (long)z * bsC;

    const int mb = (warp >> 2) * 64;     // warp M offset (2 rows of warps)
    const int nb = (warp & 3) * 32;      // warp N offset (4 cols of warps)

    float acc[4][4][4];
#pragma unroll
    for (int j = 0; j < 4; j++)
#pragma unroll
        for (int jj = 0; jj < 4; jj++)
#pragma unroll
            for (int q = 0; q < 4; q++) acc[j][jj][q] = 0.0f;

    // staging coords: 1024 float4 slots per tile -> 128 rows x 8 float4
    const int lr = tid >> 3;             // row 0..31 (+32 per i)
    const int lc = (tid & 7) * 4;        // k-col 0,4,...,28

    // ldmatrix lane addressing
    const uint32_t lrow = (uint32_t)(ln & 15);
    const uint32_t lk16 = (uint32_t)((ln >> 4) * 16);

    for (int kc = 0; kc < K; kc += 32) {
        float4 va[4], vb[4];
#pragma unroll
        for (int i = 0; i < 4; i++)
            va[i] = *(const float4*)(A + (long)(lr + i * 32) * K + kc + lc);
#pragma unroll
        for (int i = 0; i < 4; i++)
            vb[i] = *(const float4*)(B + (long)(lr + i * 32) * K + kc + lc);

        __syncthreads();     // previous chunk fully consumed (ldsm done)
#pragma unroll
        for (int i = 0; i < 4; i++) {
            uint32_t off = (uint32_t)(lr + i * 32) * PITCH + (uint32_t)lc * 2u;
            uint2 h, l;
            split4(va[i], h, l);
            *(uint2*)(sm + T_AH + off) = h;
            *(uint2*)(sm + T_AL + off) = l;
            split4(vb[i], h, l);
            *(uint2*)(sm + T_BH + off) = h;
            *(uint2*)(sm + T_BL + off) = l;
        }
        __syncthreads();     // chunk staged

#pragma unroll
        for (int h = 0; h < 2; h++) {    // two k16 halves of the 32-chunk
            uint32_t bh[8], bl[8];
#pragma unroll
            for (int t = 0; t < 2; t++) {  // 16 n-rows per ldsm4
                uint32_t ba = sbase + T_BH + (uint32_t)(nb + t * 16 + lrow) * PITCH
                            + (uint32_t)h * 32u + lk16;
                ldsm4(&bh[t * 4], ba);
                ldsm4(&bl[t * 4], ba + (T_BL - T_BH));
            }
#pragma unroll
            for (int j = 0; j < 4; j++) {
                uint32_t ah[4], al[4];
                uint32_t aa = sbase + T_AH + (uint32_t)(mb + j * 16 + lrow) * PITCH
                            + (uint32_t)h * 32u + lk16;
                ldsm4(ah, aa);
                ldsm4(al, aa + (T_AL - T_AH));
#pragma unroll
                for (int jj = 0; jj < 4; jj++) {
                    const int t = jj >> 1, s = jj & 1;
                    uint32_t bhr[2] = { bh[t * 4 + s], bh[t * 4 + 2 + s] };
                    uint32_t blr[2] = { bl[t * 4 + s], bl[t * 4 + 2 + s] };
                    hmma(acc[j][jj], ah, bhr);   // hi*hi
                    hmma(acc[j][jj], ah, blr);   // hi*lo
                    hmma(acc[j][jj], al, bhr);   // lo*hi
                }
            }
        }
    }

    // ---- epilogue ----
    const int g = ln >> 2, tig = ln & 3;
#pragma unroll
    for (int j = 0; j < 4; j++) {
        const int mlo = m0 + mb + j * 16 + g;
        const float rs0 = DO_RS ? rowscale[(long)z * M + mlo]     : 1.0f;
        const float rs1 = DO_RS ? rowscale[(long)z * M + mlo + 8] : 1.0f;
#pragma unroll
        for (int jj = 0; jj < 4; jj++) {
            const int n = n0 + nb + jj * 8 + tig * 2;
            float b0 = 0.0f, b1 = 0.0f;
            if (DO_BIAS) { b0 = bias[n]; b1 = bias[n + 1]; }
            float v0 = acc[j][jj][0], v1 = acc[j][jj][1];
            float v2 = acc[j][jj][2], v3 = acc[j][jj][3];
            if (DO_EXP) {
                v0 = __expf(v0 * alpha); v1 = __expf(v1 * alpha);
                v2 = __expf(v2 * alpha); v3 = __expf(v3 * alpha);
            }
            v0 = v0 * rs0 + b0; v1 = v1 * rs0 + b1;
            v2 = v2 * rs1 + b0; v3 = v3 * rs1 + b1;
            *(float2*)(C + (long)mlo * N + n)       = make_float2(v0, v1);
            *(float2*)(C + (long)(mlo + 8) * N + n) = make_float2(v2, v3);
        }
    }
}

// ---------------------------------------------------------------------------
// Small helper kernels
// ---------------------------------------------------------------------------
// dst[Cc][R] = src[R][Cc]^T   (R, Cc multiples of 32). block (32,8)
__global__ void transposeK(const float* __restrict__ src, float* __restrict__ dst,
                           int R, int Cc)
{
    __shared__ float t[32][33];
    int bx = blockIdx.x * 32, by = blockIdx.y * 32;
#pragma unroll
    for (int i = 0; i < 32; i += 8)
        t[threadIdx.y + i][threadIdx.x] = src[(long)(by + threadIdx.y + i) * Cc + bx + threadIdx.x];
    __syncthreads();
#pragma unroll
    for (int i = 0; i < 32; i += 8)
        dst[(long)(bx + threadIdx.y + i) * R + by + threadIdx.x] = t[threadIdx.x][threadIdx.y + i];
}

// bo2[d] = sum_m bv[m] * Wo[m,d] + bo[d]
__global__ void make_bo2(const float* __restrict__ bv, const float* __restrict__ Wo,
                         const float* __restrict__ bo, float* __restrict__ bo2)
{
    const int d = blockIdx.x * blockDim.x + threadIdx.x;   // 0..511
    float s = bo[d];
    for (int m = 0; m < DQ_; m++) s += bv[m] * Wo[m * DQ_ + d];
    bo2[d] = s;
}

// R[row] = 1 / sum_k E[row,k].  8 rows per CTA, block (32,8)
__global__ void rowsum_recip(const float* __restrict__ E, float* __restrict__ R,
                             int ncols)
{
    const int row = blockIdx.x * 8 + threadIdx.y;
    const float4* p = (const float4*)(E + (long)row * ncols);
    float s = 0.0f;
    for (int i = threadIdx.x; i < (ncols >> 2); i += 32) {
        float4 v = p[i];
        s += (v.x + v.y) + (v.z + v.w);
    }
#pragma unroll
    for (int o = 16; o > 0; o >>= 1) s += __shfl_xor_sync(0xffffffffu, s, o);
    if (threadIdx.x == 0) R[row] = 1.0f / s;
}

// ---------------------------------------------------------------------------
// kernel_launch
// ---------------------------------------------------------------------------
extern "C" void kernel_launch(void* const* d_in, const int* in_sizes, int n_in,
                              void* d_out, int out_size)
{
    (void)in_sizes; (void)n_in; (void)out_size;
    const float* query = (const float*)d_in[0];
    const float* key   = (const float*)d_in[1];
    const float* value = (const float*)d_in[2];
    const float* Wk    = (const float*)d_in[3];
    const float* bk    = (const float*)d_in[4];
    const float* Wv    = (const float*)d_in[5];
    const float* bv    = (const float*)d_in[6];
    const float* Wo    = (const float*)d_in[7];
    const float* bo    = (const float*)d_in[8];
    float* out = (float*)d_out;

    float *Kp, *VpT, *E, *R, *WkT, *WoT, *WvoT, *bo2;
    cudaGetSymbolAddress((void**)&Kp,   g_Kp);
    cudaGetSymbolAddress((void**)&VpT,  g_VpT);
    cudaGetSymbolAddress((void**)&E,    g_E);
    cudaGetSymbolAddress((void**)&R,    g_R);
    cudaGetSymbolAddress((void**)&WkT,  g_WkT);
    cudaGetSymbolAddress((void**)&WoT,  g_WoT);
    cudaGetSymbolAddress((void**)&WvoT, g_WvoT);
    cudaGetSymbolAddress((void**)&bo2,  g_bo2);

    // 0) weight transposes + folded bias
    transposeK<<<dim3(DQ_/32, DC_/32), dim3(32, 8)>>>(Wk, WkT, DC_, DQ_);  // [512,768]
    transposeK<<<dim3(DQ_/32, DQ_/32), dim3(32, 8)>>>(Wo, WoT, DQ_, DQ_);  // [512,512]
    make_bo2<<<2, 256>>>(bv, Wo, bo, bo2);

    // 1) WvoT[d,c] = sum_e WoT[d,e] * Wv[c,e]       M=512 N=768 K=512
    tgemm<0,0,0><<<dim3(6, 4, 1), 256>>>(
        WoT, Wv, WvoT, 512, 768, 512, 0, 0, 0, nullptr, nullptr, 1.0f);

    // 2) Kp = key @ WkT^T + bk                      M=2048 N=512 K=768, batched
    tgemm<0,0,1><<<dim3(4, 16, 8), 256>>>(
        key, WkT, Kp, 2048, 512, 768,
        (long)2048 * 768, 0, (long)2048 * 512, bk, nullptr, 1.0f);

    // 3) VpT = WvoT @ value^T                       M=512 N=2048 K=768, batched
    tgemm<0,0,0><<<dim3(16, 4, 8), 256>>>(
        WvoT, value, VpT, 512, 2048, 768,
        0, (long)2048 * 768, (long)512 * 2048, nullptr, nullptr, 1.0f);

    // 4) E = exp(scale * query @ Kp^T)              M=2048 N=2048 K=512, batched
    tgemm<1,0,0><<<dim3(16, 16, 8), 256>>>(
        query, Kp, E, 2048, 2048, 512,
        (long)2048 * 512, (long)2048 * 512, (long)2048 * 2048,
        nullptr, nullptr, ATT_SCALE);

    // 5) R = 1 / rowsum(E)
    rowsum_recip<<<(B_ * LQ_) / 8, dim3(32, 8)>>>(E, R, LKV_);

    // 6) out = diag(R) * (E @ VpT^T) + bo2          M=2048 N=512 K=2048, batched
    tgemm<0,1,1><<<dim3(4, 16, 8), 256>>>(
        E, VpT, out, 2048, 512, 2048,
        (long)2048 * 2048, (long)512 * 2048, (long)2048 * 512,
        bo2, R, 1.0f);
}